// round 6
// baseline (speedup 1.0000x reference)
#include <cuda_runtime.h>

// ---------------------------------------------------------------------------
// yolo_detect_target — single-wave coalesced kernel.
// grid = min(148, needed) blocks (one wave, no stragglers), 512 threads.
// Phase 1: block loads its row-slice fully coalesced, per-float4-chunk max
//          -> padded smem. Phase 2: thread-per-row reduce + box sum;
//          deterministic fixed-point atomic total. Rare paths (early conf
//          break, row-0 fail -> global max) run in the last block only.
// ---------------------------------------------------------------------------

#define CONF_T   0.25f
#define THREADS  512
#define NSM      148
#define CPR      20                  // float4 chunks per row (C=80)
#define ROWS_MAX 256                 // per-block row cap (smem sizing)
#define FXSCALE  4294967296.0        // 2^32

__device__ unsigned long long g_fx         = 0ull;
__device__ int                g_first_fail = 0x7fffffff;
__device__ unsigned           g_done       = 0u;

__device__ __forceinline__ float warp_max(float m) {
    #pragma unroll
    for (int off = 16; off; off >>= 1)
        m = fmaxf(m, __shfl_xor_sync(0xffffffffu, m, off));
    return m;
}
__device__ __forceinline__ float warp_sum(float s) {
    #pragma unroll
    for (int off = 16; off; off >>= 1)
        s += __shfl_xor_sync(0xffffffffu, s, off);
    return s;
}

// single-thread row max (rare-path / generic C)
__device__ __forceinline__ float row_max(const float* __restrict__ post,
                                         int row, int C) {
    float m = -3.4e38f;
    if (C == 80) {
        const float4* p = (const float4*)(post + (size_t)row * 80);
        #pragma unroll
        for (int i = 0; i < 20; i++) {
            float4 v = __ldg(p + i);
            m = fmaxf(m, fmaxf(fmaxf(v.x, v.y), fmaxf(v.z, v.w)));
        }
    } else {
        const float* p = post + (size_t)row * (size_t)C;
        for (int c = 0; c < C; c++) m = fmaxf(m, __ldg(p + c));
    }
    return m;
}

__global__ __launch_bounds__(THREADS)
void k_fused(const float* __restrict__ post,
             const float* __restrict__ boxes,
             int num, int rows_pb, int C, long long total_elems,
             float* __restrict__ out)
{
    const int lane = threadIdx.x & 31;
    const int wid  = threadIdx.x >> 5;
    __shared__ float cmax[ROWS_MAX * (CPR + 1)];   // pad 21 -> conflict-free
    __shared__ bool  sh_last;
    __shared__ float sh_red[THREADS / 32];

    const int r0 = blockIdx.x * rows_pb;
    int rows_here = num - r0;
    if (rows_here > rows_pb) rows_here = rows_pb;
    if (rows_here < 0) rows_here = 0;

    float val = 0.0f;

    if (C == 80) {
        // ---- phase 1: coalesced chunk loads + per-chunk max --------------
        const float4* p4 = (const float4*)post + (long long)r0 * CPR;
        const int nchunks = rows_here * CPR;
        for (int lc = threadIdx.x; lc < nchunks; lc += THREADS) {
            float4 v = __ldg(p4 + lc);
            float m3 = fmaxf(fmaxf(v.x, v.y), fmaxf(v.z, v.w));
            int r = lc / CPR;
            int c = lc - r * CPR;
            cmax[r * (CPR + 1) + c] = m3;
        }
        __syncthreads();

        // ---- phase 2: thread-per-row reduce from smem --------------------
        if (threadIdx.x < rows_here) {
            const float* cm = &cmax[threadIdx.x * (CPR + 1)];
            float m = cm[0];
            #pragma unroll
            for (int c = 1; c < CPR; c++) m = fmaxf(m, cm[c]);
            float4 b = __ldg((const float4*)boxes + (r0 + threadIdx.x));
            val = m + ((b.x + b.y) + (b.z + b.w));
            if (!(m >= CONF_T)) atomicMin(&g_first_fail, r0 + threadIdx.x);
        }
    } else {
        // generic path (not hit for this shape)
        if (threadIdx.x < rows_here) {
            int row = r0 + threadIdx.x;
            float m = row_max(post, row, C);
            float4 b = __ldg((const float4*)boxes + row);
            val = m + ((b.x + b.y) + (b.z + b.w));
            if (!(m >= CONF_T)) atomicMin(&g_first_fail, row);
        }
    }

    // ---- deterministic accumulate (only warps that hold rows) ------------
    float s = warp_sum(val);
    if (lane == 0 && wid * 32 < rows_here) {
        long long fx = __double2ll_rn((double)s * FXSCALE);
        atomicAdd(&g_fx, (unsigned long long)fx);
    }

    // ---- completion counter ---------------------------------------------
    __threadfence();
    __syncthreads();
    if (threadIdx.x == 0)
        sh_last = (atomicAdd(&g_done, 1u) == gridDim.x - 1);
    __syncthreads();
    if (!sh_last) return;

    // ================= last block: finalize ===============================
    const int K = (g_first_fail < num) ? g_first_fail : num;

    if (K >= num) {
        if (threadIdx.x == 0)
            out[0] = (float)((double)(long long)g_fx / FXSCALE);
    } else if (K == 0) {
        // rare: row 0 failed -> loss = max over all of post
        float m = -3.4e38f;
        const long long n4 = total_elems >> 2;
        const float4* p4 = (const float4*)post;
        for (long long i = threadIdx.x; i < n4; i += THREADS) {
            float4 v = p4[i];
            m = fmaxf(m, fmaxf(fmaxf(v.x, v.y), fmaxf(v.z, v.w)));
        }
        for (long long i = (n4 << 2) + threadIdx.x; i < total_elems; i += THREADS)
            m = fmaxf(m, post[i]);
        m = warp_max(m);
        if (lane == 0) sh_red[wid] = m;
        __syncthreads();
        if (wid == 0) {
            m = (lane < THREADS / 32) ? sh_red[lane] : -3.4e38f;
            m = warp_max(m);
            if (lane == 0) out[0] = m;
        }
    } else {
        // rare: early break at K -> recompute sum over rows [0, K)
        float s2 = 0.0f;
        for (int r = threadIdx.x; r < K; r += THREADS) {
            float m = row_max(post, r, C);
            float4 b = __ldg((const float4*)boxes + r);
            s2 += m + ((b.x + b.y) + (b.z + b.w));
        }
        s2 = warp_sum(s2);
        if (lane == 0) sh_red[wid] = s2;
        __syncthreads();
        if (wid == 0) {
            s2 = (lane < THREADS / 32) ? sh_red[lane] : 0.0f;
            s2 = warp_sum(s2);
            if (lane == 0) out[0] = s2;
        }
    }

    // ---- self-reset for next graph replay --------------------------------
    __syncthreads();
    if (threadIdx.x == 0) {
        g_fx         = 0ull;
        g_first_fail = 0x7fffffff;
        g_done       = 0u;
    }
}

extern "C" void kernel_launch(void* const* d_in, const int* in_sizes, int n_in,
                              void* d_out, int out_size)
{
    const float* post  = (const float*)d_in[0];   // [N, C] fp32
    const float* boxes = (const float*)d_in[1];   // [N, 4] fp32
    const long long total = (long long)in_sizes[0];
    const int N = in_sizes[1] / 4;
    const int C = (int)(total / N);

    int num = (int)((double)N * 0.02);
    if (num < 1) num = 1;
    if (num > N) num = N;

    // single wave: at most NSM blocks; rows per block capped by smem sizing
    int blocks  = (num < NSM) ? num : NSM;
    int rows_pb = (num + blocks - 1) / blocks;
    if (rows_pb > ROWS_MAX) {                 // huge num (not this shape)
        rows_pb = ROWS_MAX;
        blocks  = (num + rows_pb - 1) / rows_pb;
    }
    k_fused<<<blocks, THREADS>>>(post, boxes, num, rows_pb, C, total,
                                 (float*)d_out);
}

// round 7
// speedup vs baseline: 1.0295x; 1.0295x over previous
#include <cuda_runtime.h>

// ---------------------------------------------------------------------------
// yolo_detect_target — coalesced, load-batched (MLP=5), 1-atomic-per-block.
// Phase 1: 512 threads x 5 batched float4 loads (registers first, then
//          chunk-max -> padded smem). Phase 2: thread-per-row reduce + box.
// Block reduction -> single fixed-point atomicAdd (deterministic: integer
// adds commute). Rare paths (early conf break, row-0 fail -> global max)
// run in the last block only.
// ---------------------------------------------------------------------------

#define CONF_T   0.25f
#define THREADS  512
#define ROWS_PB  128
#define CPR      20                    // float4 chunks per row (C=80)
#define CHUNKS_PB (ROWS_PB * CPR)      // 2560 = 5 * 512
#define ITERS    (CHUNKS_PB / THREADS) // 5
#define FXSCALE  4294967296.0          // 2^32

__device__ unsigned long long g_fx         = 0ull;
__device__ int                g_first_fail = 0x7fffffff;
__device__ unsigned           g_done       = 0u;

__device__ __forceinline__ float warp_max(float m) {
    #pragma unroll
    for (int off = 16; off; off >>= 1)
        m = fmaxf(m, __shfl_xor_sync(0xffffffffu, m, off));
    return m;
}
__device__ __forceinline__ float warp_sum(float s) {
    #pragma unroll
    for (int off = 16; off; off >>= 1)
        s += __shfl_xor_sync(0xffffffffu, s, off);
    return s;
}

__device__ __forceinline__ float row_max(const float* __restrict__ post,
                                         int row, int C) {
    float m = -3.4e38f;
    if (C == 80) {
        const float4* p = (const float4*)(post + (size_t)row * 80);
        #pragma unroll
        for (int i = 0; i < 20; i++) {
            float4 v = __ldg(p + i);
            m = fmaxf(m, fmaxf(fmaxf(v.x, v.y), fmaxf(v.z, v.w)));
        }
    } else {
        const float* p = post + (size_t)row * (size_t)C;
        for (int c = 0; c < C; c++) m = fmaxf(m, __ldg(p + c));
    }
    return m;
}

__global__ __launch_bounds__(THREADS)
void k_fused(const float* __restrict__ post,
             const float* __restrict__ boxes,
             int num, int C, long long total_elems,
             float* __restrict__ out)
{
    const int lane = threadIdx.x & 31;
    const int wid  = threadIdx.x >> 5;
    __shared__ float cmax[ROWS_PB * (CPR + 1)];   // pad 21: phase-2 conflict-free
    __shared__ bool  sh_last;
    __shared__ float sh_red[THREADS / 32];

    const int r0 = blockIdx.x * ROWS_PB;
    int rows_here = num - r0;
    if (rows_here > ROWS_PB) rows_here = ROWS_PB;
    if (rows_here < 0) rows_here = 0;

    float val = 0.0f;

    if (C == 80) {
        // ---- phase 1: batched coalesced loads (MLP=ITERS), then max+STS --
        const float4* p4 = (const float4*)post + (long long)r0 * CPR;
        const int nchunks = rows_here * CPR;
        float4 v[ITERS];
        #pragma unroll
        for (int i = 0; i < ITERS; i++) {
            int lc = i * THREADS + threadIdx.x;
            if (lc < nchunks) v[i] = __ldg(p4 + lc);
            else              v[i] = make_float4(0.f, 0.f, 0.f, 0.f);
        }
        #pragma unroll
        for (int i = 0; i < ITERS; i++) {
            int lc = i * THREADS + threadIdx.x;
            float m3 = fmaxf(fmaxf(v[i].x, v[i].y), fmaxf(v[i].z, v[i].w));
            int r = lc / CPR;
            int c = lc - r * CPR;
            if (lc < CHUNKS_PB) cmax[r * (CPR + 1) + c] = m3;
        }
        __syncthreads();

        // ---- phase 2: thread-per-row reduce from smem --------------------
        if (threadIdx.x < rows_here) {
            const float* cm = &cmax[threadIdx.x * (CPR + 1)];
            float m = cm[0];
            #pragma unroll
            for (int c = 1; c < CPR; c++) m = fmaxf(m, cm[c]);
            float4 b = __ldg((const float4*)boxes + (r0 + threadIdx.x));
            val = m + ((b.x + b.y) + (b.z + b.w));
            if (!(m >= CONF_T)) atomicMin(&g_first_fail, r0 + threadIdx.x);
        }
    } else {
        // generic path (not hit for this shape)
        if (threadIdx.x < rows_here) {
            int row = r0 + threadIdx.x;
            float m = row_max(post, row, C);
            float4 b = __ldg((const float4*)boxes + row);
            val = m + ((b.x + b.y) + (b.z + b.w));
            if (!(m >= CONF_T)) atomicMin(&g_first_fail, row);
        }
    }

    // ---- full block reduction -> ONE atomic per block ---------------------
    float s = warp_sum(val);
    if (lane == 0) sh_red[wid] = s;
    __syncthreads();
    if (wid == 0) {
        s = (lane < THREADS / 32) ? sh_red[lane] : 0.0f;
        s = warp_sum(s);
        if (lane == 0) {
            long long fx = __double2ll_rn((double)s * FXSCALE);
            atomicAdd(&g_fx, (unsigned long long)fx);
        }
    }

    // ---- completion counter ----------------------------------------------
    __threadfence();
    __syncthreads();
    if (threadIdx.x == 0)
        sh_last = (atomicAdd(&g_done, 1u) == gridDim.x - 1);
    __syncthreads();
    if (!sh_last) return;

    // ================= last block: finalize ================================
    const int K = (g_first_fail < num) ? g_first_fail : num;

    if (K >= num) {
        if (threadIdx.x == 0)
            out[0] = (float)((double)(long long)g_fx / FXSCALE);
    } else if (K == 0) {
        // rare: row 0 failed -> loss = max over all of post
        float m = -3.4e38f;
        const long long n4 = total_elems >> 2;
        const float4* p4 = (const float4*)post;
        for (long long i = threadIdx.x; i < n4; i += THREADS) {
            float4 v = p4[i];
            m = fmaxf(m, fmaxf(fmaxf(v.x, v.y), fmaxf(v.z, v.w)));
        }
        for (long long i = (n4 << 2) + threadIdx.x; i < total_elems; i += THREADS)
            m = fmaxf(m, post[i]);
        m = warp_max(m);
        if (lane == 0) sh_red[wid] = m;
        __syncthreads();
        if (wid == 0) {
            m = (lane < THREADS / 32) ? sh_red[lane] : -3.4e38f;
            m = warp_max(m);
            if (lane == 0) out[0] = m;
        }
    } else {
        // rare: early break at K -> recompute sum over rows [0, K)
        float s2 = 0.0f;
        for (int r = threadIdx.x; r < K; r += THREADS) {
            float m = row_max(post, r, C);
            float4 b = __ldg((const float4*)boxes + r);
            s2 += m + ((b.x + b.y) + (b.z + b.w));
        }
        s2 = warp_sum(s2);
        __syncthreads();
        if (lane == 0) sh_red[wid] = s2;
        __syncthreads();
        if (wid == 0) {
            s2 = (lane < THREADS / 32) ? sh_red[lane] : 0.0f;
            s2 = warp_sum(s2);
            if (lane == 0) out[0] = s2;
        }
    }

    // ---- self-reset for next graph replay ---------------------------------
    __syncthreads();
    if (threadIdx.x == 0) {
        g_fx         = 0ull;
        g_first_fail = 0x7fffffff;
        g_done       = 0u;
    }
}

extern "C" void kernel_launch(void* const* d_in, const int* in_sizes, int n_in,
                              void* d_out, int out_size)
{
    const float* post  = (const float*)d_in[0];   // [N, C] fp32
    const float* boxes = (const float*)d_in[1];   // [N, 4] fp32
    const long long total = (long long)in_sizes[0];
    const int N = in_sizes[1] / 4;
    const int C = (int)(total / N);

    int num = (int)((double)N * 0.02);
    if (num < 1) num = 1;
    if (num > N) num = N;

    int blocks = (num + ROWS_PB - 1) / ROWS_PB;   // 157 for num=20000
    k_fused<<<blocks, THREADS>>>(post, boxes, num, C, total, (float*)d_out);
}